// round 12
// baseline (speedup 1.0000x reference)
#include <cuda_runtime.h>
#include <cuda_fp16.h>
#include <math.h>

#define NN 200000
#define EE 6400000
#define MM 10000
#define NBIN 444           // bins; 444 = 3 * 148 SMs -> 3 exact fine waves
#define NPB 451            // nodes per bin; 451*444 = 200244 >= NN
#define CAP 15360          // pair capacity per bin; mean 14414, 7.9 sigma
#define COARSE_BLOCKS 1563 // ceil(1.6M int4 / 1024)
#define GEMM_BLOCKS 3125   // 200000 / 64
#define SCALE_BLOCKS 3125  // 200000*16 floats / 4 / 256
#define NGRP 16            // coarse rank-counter groups (2 warps per group)

// ---------------- device scratch (no allocations allowed) ----------------
__device__ __align__(16) int    g_ccur[NBIN];             // coarse bin cursors/counts
__device__ __align__(16) int2   g_pairs[(size_t)NBIN * CAP]; // (src,dst) per bin (54.6MB)
__device__ __align__(16) int    g_cnt[NN];                // in-degree
__device__ __align__(16) int    g_off[NN];                // packed CSR offsets
__device__ __align__(16) int    g_csr[EE];                // packed adjacency
__device__                 char g_need[NN];
__device__ __align__(16) float  g_h1[(size_t)NN * 16];    // x@W1 (raw, fp32)
__device__ __align__(16) __half g_h1h[(size_t)NN * 16];   // dinv * (x@W1), fp16
__device__ __align__(16) float  g_hw2[(size_t)NN * 2];    // dinv * (relu(l1) @ W2)
__device__ __align__(16) float  g_bp[MM * 5];
__device__ __align__(16) unsigned g_minmax[2];

// ordered-uint encoding so unsigned atomicMin/Max give float min/max
__device__ __forceinline__ unsigned fenc(float f) {
    unsigned u = __float_as_uint(f);
    return (u & 0x80000000u) ? ~u : (u | 0x80000000u);
}
__device__ __forceinline__ float fdec(unsigned u) {
    return (u & 0x80000000u) ? __uint_as_float(u & 0x7fffffffu)
                             : __uint_as_float(~u);
}

// ---------------- kernels ----------------

__global__ void k_zero() {
    int i = blockIdx.x * blockDim.x + threadIdx.x;
    if (i < NN) g_need[i] = ((i % 20) == 0) ? 1 : 0;
    if (i < NBIN) g_ccur[i] = 0;
    if (i == 0) { g_minmax[0] = 0xFFFFFFFFu; g_minmax[1] = 0u; }
}

// Fused: coarse bucket sort of edges by dst-bin (blocks [0, COARSE_BLOCKS))
//        || x@W1 GEMM (rest).
// Coarse: smem per-group rank counters + ONE global atomic per (block,bin)
// -> global atomics drop 6.4M -> ~0.7M; stores are per-bin streams.
__global__ void __launch_bounds__(1024) k_coarse_gemm(
        const int* __restrict__ src, const int* __restrict__ dst,
        const float* __restrict__ x, const float* __restrict__ W1) {
    __shared__ __align__(16) char um[32000];
    int t = threadIdx.x;
    if (blockIdx.x < COARSE_BLOCKS) {
        int* scnt   = (int*)um;               // [NGRP][NBIN]
        int* sgbase = (int*)(um + NGRP * NBIN * 4);  // [NBIN]
        int g = t >> 6;                        // 2 warps per group
        for (int i = t; i < NGRP * NBIN; i += 1024) scnt[i] = 0;
        __syncthreads();

        int i4 = blockIdx.x * 1024 + t;        // int4 slot
        bool act = (i4 < EE / 4);
        int4 s4 = act ? ((const int4*)src)[i4] : make_int4(0,0,0,0);
        int4 d4 = act ? ((const int4*)dst)[i4] : make_int4(0,0,0,0);
        int ss[4] = { s4.x, s4.y, s4.z, s4.w };
        int dd[4] = { d4.x, d4.y, d4.z, d4.w };
        int bin[4], r[4];
        if (act) {
#pragma unroll
            for (int k = 0; k < 4; k++) {
                bin[k] = dd[k] / NPB;
                r[k] = atomicAdd(&scnt[g * NBIN + bin[k]], 1);
            }
        }
        __syncthreads();
        // per-bin: prefix over the 16 groups, claim block total globally
        if (t < NBIN) {
            int run = 0;
#pragma unroll
            for (int gg = 0; gg < NGRP; gg++) {
                int c = scnt[gg * NBIN + t];
                scnt[gg * NBIN + t] = run;
                run += c;
            }
            sgbase[t] = (run > 0) ? atomicAdd(&g_ccur[t], run) : 0;
        }
        __syncthreads();
        if (act) {
#pragma unroll
            for (int k = 0; k < 4; k++) {
                int pos = sgbase[bin[k]] + scnt[g * NBIN + bin[k]] + r[k];
                g_pairs[(size_t)bin[k] * CAP + pos] = make_int2(ss[k], dd[k]);
            }
        }
        return;
    }
    // ---- GEMM branch: 64 rows x 16 cols per block, 1024 threads ----
    float* sx = (float*)um;            // 6400 floats
    float* sw = (float*)(um + 25600);  // 1600 floats
    int b = blockIdx.x - COARSE_BLOCKS;
    size_t row0 = (size_t)b * 64;
    const float4* xg = (const float4*)(x + row0 * 100);
    float4* sx4 = (float4*)sx;
    for (int i = t; i < 1600; i += 1024) sx4[i] = xg[i];
    if (t < 400) ((float4*)sw)[t] = ((const float4*)W1)[t];
    __syncthreads();
    int j = t & 15, rg = t >> 4;       // rg 0..63
    float a = 0.f;
#pragma unroll 4
    for (int k = 0; k < 100; k++) a += sx[rg * 100 + k] * sw[k * 16 + j];
    g_h1[(row0 + rg) * 16 + j] = a;
}

// Fine pass: one block per bin. Per-node histogram + scan + placement all in
// SMEM; emits g_cnt/g_off (no separate scan kernel) and packed g_csr whose
// stores land in a ~58KB hot window.
__global__ void __launch_bounds__(512) k_fine() {
    __shared__ int scnt[512];
    __shared__ int sscan[512];
    int b = blockIdx.x, t = threadIdx.x;
    int nb = g_ccur[b];
    // packed CSR base for this bin: exclusive scan of bin counts
    sscan[t] = (t < NBIN) ? g_ccur[t] : 0;
    __syncthreads();
    for (int o = 1; o < 512; o <<= 1) {
        int u = (t >= o) ? sscan[t - o] : 0;
        __syncthreads(); sscan[t] += u; __syncthreads();
    }
    int bin_base = sscan[b] - nb;
    __syncthreads();
    scnt[t] = 0;
    __syncthreads();
    const int2* pr = g_pairs + (size_t)b * CAP;
    int nodebase = b * NPB;
    for (int i = t; i < nb; i += 512)
        atomicAdd(&scnt[pr[i].y - nodebase], 1);
    __syncthreads();
    int c = scnt[t];
    sscan[t] = c;
    __syncthreads();
    for (int o = 1; o < 512; o <<= 1) {
        int u = (t >= o) ? sscan[t - o] : 0;
        __syncthreads(); sscan[t] += u; __syncthreads();
    }
    int excl = sscan[t] - c;
    int node = nodebase + t;
    if (t < NPB && node < NN) { g_cnt[node] = c; g_off[node] = bin_base + excl; }
    __syncthreads();
    scnt[t] = excl;                      // cursors
    __syncthreads();
    for (int i = t; i < nb; i += 512) {
        int2 p = pr[i];
        int pos = atomicAdd(&scnt[p.y - nodebase], 1);
        g_csr[bin_base + pos] = p.x;
        if (p.y % 20 == 0) g_need[p.x] = 1;
    }
}

// h1h = fp16(dinv * h1). Counts final after k_fine.
__global__ void k_scale() {
    int i = blockIdx.x * 256 + threadIdx.x;   // float4 index into g_h1 (800000)
    int row = i >> 2;
    float dv = rsqrtf((float)__ldg(&g_cnt[row]) + 1.0f);
    float4 v = ((const float4*)g_h1)[i];
    __half2 ha = __floats2half2_rn(v.x * dv, v.y * dv);
    __half2 hb = __floats2half2_rn(v.z * dv, v.w * dv);
    uint2 o;
    o.x = *reinterpret_cast<unsigned*>(&ha);
    o.y = *reinterpret_cast<unsigned*>(&hb);
    ((uint2*)g_h1h)[i] = o;
}

// Pull aggregation layer 1: 4 nodes per warp, 8 lanes per node.
// Lane k owns half2 column pair (2k, 2k+1); serial accumulation over the
// node's contiguous CSR segment. Fused bias + relu + (@W2) + dinv epilogue.
__global__ void k_pass1(const float* __restrict__ b1, const float* __restrict__ W2) {
    int gw = (blockIdx.x * blockDim.x + threadIdx.x) >> 5;   // 50000 warps
    int lane = threadIdx.x & 31;
    int nl = lane >> 3, k = lane & 7;
    int node = gw * 4 + nl;                                  // exact: 50000*4 = NN
    bool need = g_need[node];
    int ndeg = need ? __ldg(&g_cnt[node]) : 0;
    int off  = __ldg(&g_off[node]);
    const unsigned FULL = 0xffffffffu;

    float ax = 0.f, ay = 0.f;
#pragma unroll 4
    for (int i = 0; i < ndeg; i++) {
        int s = __ldg(&g_csr[off + i]);                      // broadcast in group
        float2 f = __half22float2(__ldg((const __half2*)(g_h1h + (size_t)s * 16 + 2 * k)));
        ax += f.x; ay += f.y;
    }
    {   // self term (h1h already has dinv folded in)
        float2 f = __half22float2(__ldg((const __half2*)(g_h1h + (size_t)node * 16 + 2 * k)));
        ax += f.x; ay += f.y;
    }
    float dv = rsqrtf((float)ndeg + 1.0f);
    float r0 = fmaxf(dv * ax + __ldg(&b1[2 * k + 0]), 0.f);
    float r1 = fmaxf(dv * ay + __ldg(&b1[2 * k + 1]), 0.f);
    float p0 = r0 * __ldg(&W2[(2 * k + 0) * 2 + 0]) + r1 * __ldg(&W2[(2 * k + 1) * 2 + 0]);
    float p1 = r0 * __ldg(&W2[(2 * k + 0) * 2 + 1]) + r1 * __ldg(&W2[(2 * k + 1) * 2 + 1]);
    p0 += __shfl_xor_sync(FULL, p0, 1); p1 += __shfl_xor_sync(FULL, p1, 1);
    p0 += __shfl_xor_sync(FULL, p0, 2); p1 += __shfl_xor_sync(FULL, p1, 2);
    p0 += __shfl_xor_sync(FULL, p0, 4); p1 += __shfl_xor_sync(FULL, p1, 4);
    if (k == 0 && need) {
        float2 o; o.x = dv * p0; o.y = dv * p1;
        *(float2*)&g_hw2[(size_t)node * 2] = o;
    }
}

// Layer-2 aggregation only for nodes d=20m, fused bias + log_softmax + BP + min/max.
__global__ void k_pass2(const float* __restrict__ tE, const float* __restrict__ cE,
                        const float* __restrict__ pE, const float* __restrict__ b2) {
    int warp = (blockIdx.x * blockDim.x + threadIdx.x) >> 5;
    int lane = threadIdx.x & 31;
    if (warp >= MM) return;
    int m = warp;
    int d = m * 20;
    int ndeg = __ldg(&g_cnt[d]);
    int off  = __ldg(&g_off[d]);
    float a0 = 0.f, a1 = 0.f;
    for (int i = lane; i < ndeg; i += 32) {
        int s = __ldg(&g_csr[off + i]);
        float2 v = *reinterpret_cast<const float2*>(&g_hw2[(size_t)s * 2]);
        a0 += v.x; a1 += v.y;
    }
    const unsigned FULL = 0xffffffffu;
#pragma unroll
    for (int o = 16; o > 0; o >>= 1) {
        a0 += __shfl_xor_sync(FULL, a0, o);
        a1 += __shfl_xor_sync(FULL, a1, o);
    }
    if (lane == 0) {
        float2 sv = *reinterpret_cast<const float2*>(&g_hw2[(size_t)d * 2]);
        a0 += sv.x; a1 += sv.y;
        float dv = rsqrtf((float)ndeg + 1.0f);
        float z0 = dv * a0 + __ldg(&b2[0]);
        float z1 = dv * a1 + __ldg(&b2[1]);
        float mx = fmaxf(z0, z1);
        float lse = mx + logf(expf(z0 - mx) + expf(z1 - mx));
        float ls0 = z0 - lse, ls1 = z1 - lse;
        float v0 = __ldg(&tE[m]), v1 = __ldg(&cE[m]), v2 = __ldg(&pE[m]);
        g_bp[m * 5 + 0] = v0;
        g_bp[m * 5 + 1] = v1;
        g_bp[m * 5 + 2] = v2;
        g_bp[m * 5 + 3] = ls0;
        g_bp[m * 5 + 4] = ls1;
        float mn  = fminf(fminf(v0, v1), fminf(v2, fminf(ls0, ls1)));
        float mxv = fmaxf(fmaxf(v0, v1), fmaxf(v2, fmaxf(ls0, ls1)));
        atomicMin(&g_minmax[0], fenc(mn));
        atomicMax(&g_minmax[1], fenc(mxv));
    }
}

// min-max normalize + 5->80->10->1 MLP + sigmoid
__global__ void k_mlp(const float* __restrict__ W1, const float* __restrict__ b1,
                      const float* __restrict__ W2, const float* __restrict__ b2,
                      const float* __restrict__ W3, const float* __restrict__ b3,
                      float* __restrict__ out) {
    __shared__ float sW1[400], sb1[80], sW2[800], sb2[10], sW3[10];
    __shared__ float sb3v, smn, ssc;
    int t = threadIdx.x;
    for (int i = t; i < 400; i += 256) sW1[i] = W1[i];
    for (int i = t; i < 80;  i += 256) sb1[i] = b1[i];
    for (int i = t; i < 800; i += 256) sW2[i] = W2[i];
    if (t < 10) { sb2[t] = b2[t]; sW3[t] = W3[t]; }
    if (t == 0) {
        sb3v = b3[0];
        smn = fdec(g_minmax[0]);
        float mxv = fdec(g_minmax[1]);
        ssc = 1.0f / (mxv - smn);
    }
    __syncthreads();
    int m = blockIdx.x * blockDim.x + t;
    if (m >= MM) return;
    float in[5];
#pragma unroll
    for (int i = 0; i < 5; i++) in[i] = (g_bp[m * 5 + i] - smn) * ssc;
    float h2[10];
#pragma unroll
    for (int q = 0; q < 10; q++) h2[q] = sb2[q];
    for (int o = 0; o < 80; o++) {
        float a = sb1[o];
#pragma unroll
        for (int i = 0; i < 5; i++) a += in[i] * sW1[i * 80 + o];
        a = fmaxf(a, 0.f);
#pragma unroll
        for (int q = 0; q < 10; q++) h2[q] += a * sW2[o * 10 + q];
    }
    float v = sb3v;
#pragma unroll
    for (int q = 0; q < 10; q++) v += fmaxf(h2[q], 0.f) * sW3[q];
    out[m] = 1.0f / (1.0f + expf(-v));
}

// ---------------- launch ----------------
extern "C" void kernel_launch(void* const* d_in, const int* in_sizes, int n_in,
                              void* d_out, int out_size) {
    const int*   ei   = (const int*)d_in[0];    // batch1_edge_index [2,E]
    const float* x    = (const float*)d_in[1];  // batch1_x [N,100]
    const float* tE   = (const float*)d_in[4];
    const float* cE   = (const float*)d_in[5];
    const float* pE   = (const float*)d_in[6];
    const float* ghW1 = (const float*)d_in[8];
    const float* ghb1 = (const float*)d_in[9];
    const float* ghW2 = (const float*)d_in[10];
    const float* ghb2 = (const float*)d_in[11];
    const float* mW1  = (const float*)d_in[16];
    const float* mb1  = (const float*)d_in[17];
    const float* mW2  = (const float*)d_in[18];
    const float* mb2  = (const float*)d_in[19];
    const float* mW3  = (const float*)d_in[20];
    const float* mb3  = (const float*)d_in[21];
    // batch2_*, edit_input, gt_* are dead in the reference output — skipped.

    const int* src = ei;
    const int* dst = ei + EE;
    float* out = (float*)d_out;

    k_zero        <<<(NN + 255) / 256, 256>>>();
    k_coarse_gemm <<<COARSE_BLOCKS + GEMM_BLOCKS, 1024>>>(src, dst, x, ghW1);
    k_fine        <<<NBIN, 512>>>();
    k_scale       <<<SCALE_BLOCKS, 256>>>();
    k_pass1       <<<NN / 4 / 8, 256>>>(ghb1, ghW2);
    k_pass2       <<<MM / 8, 256>>>(tE, cE, pE, ghb2);
    k_mlp         <<<(MM + 255) / 256, 256>>>(mW1, mb1, mW2, mb2, mW3, mb3, out);
}

// round 13
// speedup vs baseline: 1.1242x; 1.1242x over previous
#include <cuda_runtime.h>
#include <cuda_fp16.h>
#include <math.h>

#define NN 200000
#define EE 6400000
#define MM 10000
#define SHARDS 4
#define SCAN_CHUNK 2048
#define SCAN_NB 98          // ceil(NN / SCAN_CHUNK)
#define HIST_BLOCKS 6250    // 6.4M edges / 4-per-thread / 256
#define GEMM_BLOCKS 3125    // 200000 / 64
#define SCAT_BLOCKS 6250
#define SCALE_BLOCKS 3125   // 200000*16 floats / 4 / 256

// ---------------- device scratch (no allocations allowed) ----------------
// Self-cleaning invariants (restored by the pipeline itself each call, and
// satisfied by BSS zero-init on the very first call):
//   g_cnt   == 0        (reset by pass1)
//   g_need  == 0        (reset by pass1; "need" = mark || node%20==0)
//   g_agg   == 0        (reset by pass1 block 0; scan publishes total+1)
//   g_minmax== {0,0}    (reset by scan thread 0; both tracked via atomicMax
//                        over strictly-positive encodings)
__device__ __align__(16) int    g_cnt[NN * SHARDS];   // sharded in-degree counters
__device__ __align__(16) int    g_off[NN];            // packed CSR row offsets
__device__ __align__(16) int    g_cursor[NN * SHARDS];// absolute sub-cursors per shard
__device__ __align__(16) int    g_agg[128];           // scan lookback aggregates
__device__ __align__(16) int    g_csr[EE];            // packed adjacency (25.6MB)
__device__                 char g_need[NN];
__device__ __align__(16) int    g_deg20[MM];          // degree of sampled nodes
__device__ __align__(16) float  g_h1[(size_t)NN * 16];    // x@W1 (raw, fp32)
__device__ __align__(16) __half g_h1h[(size_t)NN * 16];   // dinv * (x@W1), fp16
__device__ __align__(16) float  g_hw2[(size_t)NN * 2];    // dinv * (relu(l1) @ W2)
__device__ __align__(16) float  g_bp[MM * 5];
__device__ __align__(16) unsigned g_minmax[2];        // [0]=max(~fenc)->min, [1]=max(fenc)

// ordered-uint encoding so unsigned atomicMax gives float max; fenc(x) > 0
// for every real float, and ~fenc(x) > 0 likewise -> init value 0 is neutral.
__device__ __forceinline__ unsigned fenc(float f) {
    unsigned u = __float_as_uint(f);
    return (u & 0x80000000u) ? ~u : (u | 0x80000000u);
}
__device__ __forceinline__ float fdec(unsigned u) {
    return (u & 0x80000000u) ? __uint_as_float(u & 0x7fffffffu)
                             : __uint_as_float(~u);
}

// ---------------- kernels ----------------

// Fused: sharded histogram of dst (blocks [0, HIST_BLOCKS)) || x@W1 GEMM.
// Shard (t+k)&3 decorrelates same-dst edges: contention/addr 32 -> ~8.
// atomicAdd result unused -> RED (no-return).
__global__ void k_hist_gemm(const int* __restrict__ dst,
                            const float* __restrict__ x,
                            const float* __restrict__ W1) {
    __shared__ __align__(16) float sx[64 * 100];
    __shared__ __align__(16) float sw[100 * 16];
    int t = threadIdx.x;
    if (blockIdx.x < HIST_BLOCKS) {
        int i = blockIdx.x * 256 + t;          // int4 index, 6250*256 = 1.6M exactly
        int4 d = ((const int4*)dst)[i];
        atomicAdd(&g_cnt[d.x * SHARDS + ( t      & 3)], 1);
        atomicAdd(&g_cnt[d.y * SHARDS + ((t + 1) & 3)], 1);
        atomicAdd(&g_cnt[d.z * SHARDS + ((t + 2) & 3)], 1);
        atomicAdd(&g_cnt[d.w * SHARDS + ((t + 3) & 3)], 1);
        return;
    }
    int b = blockIdx.x - HIST_BLOCKS;
    size_t row0 = (size_t)b * 64;

    const float4* xg = (const float4*)(x + row0 * 100);
    float4* sx4 = (float4*)sx;
#pragma unroll
    for (int i = 0; i < 7; i++) { int idx = t + i * 256; if (idx < 1600) sx4[idx] = xg[idx]; }
    const float4* wg = (const float4*)W1;
    float4* sw4 = (float4*)sw;
#pragma unroll
    for (int i = 0; i < 2; i++) { int idx = t + i * 256; if (idx < 400) sw4[idx] = wg[idx]; }
    __syncthreads();

    int j = t & 15, rg = t >> 4;
    float a0 = 0.f, a1 = 0.f, a2 = 0.f, a3 = 0.f;
#pragma unroll 4
    for (int k = 0; k < 100; k++) {
        float w = sw[k * 16 + j];
        a0 += sx[(rg +  0) * 100 + k] * w;
        a1 += sx[(rg + 16) * 100 + k] * w;
        a2 += sx[(rg + 32) * 100 + k] * w;
        a3 += sx[(rg + 48) * 100 + k] * w;
    }
    int r0 = (int)row0;
    g_h1[(size_t)(r0 + rg +  0) * 16 + j] = a0;
    g_h1[(size_t)(r0 + rg + 16) * 16 + j] = a1;
    g_h1[(size_t)(r0 + rg + 32) * 16 + j] = a2;
    g_h1[(size_t)(r0 + rg + 48) * 16 + j] = a3;
}

// Decoupled-lookback exclusive scan of node degrees (sum of 4 shard counts)
// -> packed g_off + 4 absolute sub-cursors per node partitioning [off, off+deg).
// Publishes total+1 (nonzero) and spins on 0; g_agg pre-zeroed by prior pass1.
// Thread (0,0) also resets g_minmax for this call's pass2.
__global__ void k_scan() {
    __shared__ int sh[512];
    __shared__ int s_prefix;
    int b = blockIdx.x, t = threadIdx.x;
    int base = b * SCAN_CHUNK + t * 4;
    int4 c[4]; int deg[4]; int s = 0;
#pragma unroll
    for (int i = 0; i < 4; i++) {
        int idx = base + i;
        if (idx < NN) c[i] = *(const int4*)&g_cnt[idx * SHARDS];
        else          c[i] = make_int4(0, 0, 0, 0);
        deg[i] = c[i].x + c[i].y + c[i].z + c[i].w;
        s += deg[i];
    }
    sh[t] = s; __syncthreads();
    for (int o = 1; o < 512; o <<= 1) {
        int u = (t >= o) ? sh[t - o] : 0;
        __syncthreads();
        sh[t] += u;
        __syncthreads();
    }
    int total = sh[511];
    if (t == 0) {
        s_prefix = 0;
        if (b == 0) { g_minmax[0] = 0u; g_minmax[1] = 0u; }
        *(volatile int*)&g_agg[b] = total + 1;   // publish aggregate (nonzero)
        __threadfence();
    }
    __syncthreads();
    int pv = 0;
    if (t < b) {
        int xv;
        do { xv = *(volatile int*)&g_agg[t]; } while (xv == 0);
        pv = xv - 1;
    }
#pragma unroll
    for (int o = 16; o > 0; o >>= 1) pv += __shfl_xor_sync(0xffffffffu, pv, o);
    if ((t & 31) == 0 && pv != 0) atomicAdd(&s_prefix, pv);
    __syncthreads();
    int ex = sh[t] - s + s_prefix;
#pragma unroll
    for (int i = 0; i < 4; i++) {
        int idx = base + i;
        if (idx < NN) {
            g_off[idx] = ex;
            int4 cur;
            cur.x = ex;
            cur.y = ex + c[i].x;
            cur.z = ex + c[i].x + c[i].y;
            cur.w = ex + c[i].x + c[i].y + c[i].z;
            *(int4*)&g_cursor[idx * SHARDS] = cur;
            ex += deg[i];
        }
    }
}

// Fused: packed scatter with sharded cursors + need-mark (blocks [0,SCAT_BLOCKS))
//        || h1h = fp16(dinv * h1) (rest). Shard formula MUST match k_hist_gemm.
__global__ void k_scatter_scale(const int* __restrict__ src, const int* __restrict__ dst) {
    int t = threadIdx.x;
    if (blockIdx.x < SCAT_BLOCKS) {
        int i = blockIdx.x * 256 + t;
        int4 s4 = ((const int4*)src)[i];
        int4 d4 = ((const int4*)dst)[i];
        int p;
        p = atomicAdd(&g_cursor[d4.x * SHARDS + ( t      & 3)], 1); g_csr[p] = s4.x;
        if (d4.x % 20 == 0) g_need[s4.x] = 1;
        p = atomicAdd(&g_cursor[d4.y * SHARDS + ((t + 1) & 3)], 1); g_csr[p] = s4.y;
        if (d4.y % 20 == 0) g_need[s4.y] = 1;
        p = atomicAdd(&g_cursor[d4.z * SHARDS + ((t + 2) & 3)], 1); g_csr[p] = s4.z;
        if (d4.z % 20 == 0) g_need[s4.z] = 1;
        p = atomicAdd(&g_cursor[d4.w * SHARDS + ((t + 3) & 3)], 1); g_csr[p] = s4.w;
        if (d4.w % 20 == 0) g_need[s4.w] = 1;
        return;
    }
    int b = blockIdx.x - SCAT_BLOCKS;
    int i = b * 256 + t;                 // float4 index into g_h1 (800000 total)
    int row = i >> 2;
    int4 c4 = __ldg((const int4*)&g_cnt[row * SHARDS]);
    float dv = rsqrtf((float)(c4.x + c4.y + c4.z + c4.w) + 1.0f);
    float4 v = ((const float4*)g_h1)[i];
    __half2 ha = __floats2half2_rn(v.x * dv, v.y * dv);
    __half2 hb = __floats2half2_rn(v.z * dv, v.w * dv);
    uint2 o;
    o.x = *reinterpret_cast<unsigned*>(&ha);
    o.y = *reinterpret_cast<unsigned*>(&hb);
    ((uint2*)g_h1h)[i] = o;
}

// Pull aggregation layer 1: 4 nodes per warp, 8 lanes per node.
// Lane k owns half2 column pair (2k, 2k+1); serial accumulation over the
// node's contiguous CSR segment. Fused bias + relu + (@W2) + dinv epilogue.
// Also the state janitor: resets g_cnt/g_need for its nodes, stashes sampled
// degrees for pass2, and block 0 re-zeros g_agg for the next call's scan.
__global__ void k_pass1(const float* __restrict__ b1, const float* __restrict__ W2) {
    if (blockIdx.x == 0 && threadIdx.x < 128) g_agg[threadIdx.x] = 0;
    int gw = (blockIdx.x * blockDim.x + threadIdx.x) >> 5;   // 50000 warps
    int lane = threadIdx.x & 31;
    int nl = lane >> 3, k = lane & 7;
    int node = gw * 4 + nl;                                  // exact: 50000*4 = NN
    bool samp = (node % 20 == 0);
    bool need = g_need[node] | samp;
    int4 c4 = __ldg((const int4*)&g_cnt[node * SHARDS]);
    int ndeg = need ? (c4.x + c4.y + c4.z + c4.w) : 0;
    int off  = __ldg(&g_off[node]);
    const unsigned FULL = 0xffffffffu;

    float ax = 0.f, ay = 0.f;
#pragma unroll 4
    for (int i = 0; i < ndeg; i++) {
        int s = __ldg(&g_csr[off + i]);                      // broadcast in group
        float2 f = __half22float2(__ldg((const __half2*)(g_h1h + (size_t)s * 16 + 2 * k)));
        ax += f.x; ay += f.y;
    }
    {   // self term (h1h already has dinv folded in)
        float2 f = __half22float2(__ldg((const __half2*)(g_h1h + (size_t)node * 16 + 2 * k)));
        ax += f.x; ay += f.y;
    }
    float dv = rsqrtf((float)ndeg + 1.0f);
    float r0 = fmaxf(dv * ax + __ldg(&b1[2 * k + 0]), 0.f);
    float r1 = fmaxf(dv * ay + __ldg(&b1[2 * k + 1]), 0.f);
    float p0 = r0 * __ldg(&W2[(2 * k + 0) * 2 + 0]) + r1 * __ldg(&W2[(2 * k + 1) * 2 + 0]);
    float p1 = r0 * __ldg(&W2[(2 * k + 0) * 2 + 1]) + r1 * __ldg(&W2[(2 * k + 1) * 2 + 1]);
    p0 += __shfl_xor_sync(FULL, p0, 1); p1 += __shfl_xor_sync(FULL, p1, 1);
    p0 += __shfl_xor_sync(FULL, p0, 2); p1 += __shfl_xor_sync(FULL, p1, 2);
    p0 += __shfl_xor_sync(FULL, p0, 4); p1 += __shfl_xor_sync(FULL, p1, 4);
    if (k == 0) {
        if (need) {
            float2 o; o.x = dv * p0; o.y = dv * p1;
            *(float2*)&g_hw2[(size_t)node * 2] = o;
        }
        // self-clean for next graph replay
        *(int4*)&g_cnt[node * SHARDS] = make_int4(0, 0, 0, 0);
        g_need[node] = 0;
        if (samp) g_deg20[node / 20] = ndeg;
    }
}

// Layer-2 aggregation only for nodes d=20m, fused bias + log_softmax + BP + min/max.
__global__ void k_pass2(const float* __restrict__ tE, const float* __restrict__ cE,
                        const float* __restrict__ pE, const float* __restrict__ b2) {
    int warp = (blockIdx.x * blockDim.x + threadIdx.x) >> 5;
    int lane = threadIdx.x & 31;
    if (warp >= MM) return;
    int m = warp;
    int d = m * 20;
    int ndeg = __ldg(&g_deg20[m]);
    int off  = __ldg(&g_off[d]);
    float a0 = 0.f, a1 = 0.f;
    for (int i = lane; i < ndeg; i += 32) {
        int s = __ldg(&g_csr[off + i]);
        float2 v = *reinterpret_cast<const float2*>(&g_hw2[(size_t)s * 2]);
        a0 += v.x; a1 += v.y;
    }
    const unsigned FULL = 0xffffffffu;
#pragma unroll
    for (int o = 16; o > 0; o >>= 1) {
        a0 += __shfl_xor_sync(FULL, a0, o);
        a1 += __shfl_xor_sync(FULL, a1, o);
    }
    if (lane == 0) {
        float2 sv = *reinterpret_cast<const float2*>(&g_hw2[(size_t)d * 2]);
        a0 += sv.x; a1 += sv.y;
        float dv = rsqrtf((float)ndeg + 1.0f);
        float z0 = dv * a0 + __ldg(&b2[0]);
        float z1 = dv * a1 + __ldg(&b2[1]);
        float mx = fmaxf(z0, z1);
        float lse = mx + logf(expf(z0 - mx) + expf(z1 - mx));
        float ls0 = z0 - lse, ls1 = z1 - lse;
        float v0 = __ldg(&tE[m]), v1 = __ldg(&cE[m]), v2 = __ldg(&pE[m]);
        g_bp[m * 5 + 0] = v0;
        g_bp[m * 5 + 1] = v1;
        g_bp[m * 5 + 2] = v2;
        g_bp[m * 5 + 3] = ls0;
        g_bp[m * 5 + 4] = ls1;
        float mn  = fminf(fminf(v0, v1), fminf(v2, fminf(ls0, ls1)));
        float mxv = fmaxf(fmaxf(v0, v1), fmaxf(v2, fmaxf(ls0, ls1)));
        atomicMax(&g_minmax[0], ~fenc(mn));   // min via max of complement
        atomicMax(&g_minmax[1], fenc(mxv));
    }
}

// min-max normalize + 5->80->10->1 MLP + sigmoid
__global__ void k_mlp(const float* __restrict__ W1, const float* __restrict__ b1,
                      const float* __restrict__ W2, const float* __restrict__ b2,
                      const float* __restrict__ W3, const float* __restrict__ b3,
                      float* __restrict__ out) {
    __shared__ float sW1[400], sb1[80], sW2[800], sb2[10], sW3[10];
    __shared__ float sb3v, smn, ssc;
    int t = threadIdx.x;
    for (int i = t; i < 400; i += 256) sW1[i] = W1[i];
    for (int i = t; i < 80;  i += 256) sb1[i] = b1[i];
    for (int i = t; i < 800; i += 256) sW2[i] = W2[i];
    if (t < 10) { sb2[t] = b2[t]; sW3[t] = W3[t]; }
    if (t == 0) {
        sb3v = b3[0];
        smn = fdec(~g_minmax[0]);
        float mxv = fdec(g_minmax[1]);
        ssc = 1.0f / (mxv - smn);
    }
    __syncthreads();
    int m = blockIdx.x * blockDim.x + t;
    if (m >= MM) return;
    float in[5];
#pragma unroll
    for (int i = 0; i < 5; i++) in[i] = (g_bp[m * 5 + i] - smn) * ssc;
    float h2[10];
#pragma unroll
    for (int q = 0; q < 10; q++) h2[q] = sb2[q];
    for (int o = 0; o < 80; o++) {
        float a = sb1[o];
#pragma unroll
        for (int i = 0; i < 5; i++) a += in[i] * sW1[i * 80 + o];
        a = fmaxf(a, 0.f);
#pragma unroll
        for (int q = 0; q < 10; q++) h2[q] += a * sW2[o * 10 + q];
    }
    float v = sb3v;
#pragma unroll
    for (int q = 0; q < 10; q++) v += fmaxf(h2[q], 0.f) * sW3[q];
    out[m] = 1.0f / (1.0f + expf(-v));
}

// ---------------- launch ----------------
extern "C" void kernel_launch(void* const* d_in, const int* in_sizes, int n_in,
                              void* d_out, int out_size) {
    const int*   ei   = (const int*)d_in[0];    // batch1_edge_index [2,E]
    const float* x    = (const float*)d_in[1];  // batch1_x [N,100]
    const float* tE   = (const float*)d_in[4];
    const float* cE   = (const float*)d_in[5];
    const float* pE   = (const float*)d_in[6];
    const float* ghW1 = (const float*)d_in[8];
    const float* ghb1 = (const float*)d_in[9];
    const float* ghW2 = (const float*)d_in[10];
    const float* ghb2 = (const float*)d_in[11];
    const float* mW1  = (const float*)d_in[16];
    const float* mb1  = (const float*)d_in[17];
    const float* mW2  = (const float*)d_in[18];
    const float* mb2  = (const float*)d_in[19];
    const float* mW3  = (const float*)d_in[20];
    const float* mb3  = (const float*)d_in[21];
    // batch2_*, edit_input, gt_* are dead in the reference output — skipped.

    const int* src = ei;
    const int* dst = ei + EE;
    float* out = (float*)d_out;

    k_hist_gemm     <<<HIST_BLOCKS + GEMM_BLOCKS, 256>>>(dst, x, ghW1);
    k_scan          <<<SCAN_NB, 512>>>();
    k_scatter_scale <<<SCAT_BLOCKS + SCALE_BLOCKS, 256>>>(src, dst);
    k_pass1         <<<NN / 4 / 8, 256>>>(ghb1, ghW2);
    k_pass2         <<<MM / 8, 256>>>(tE, cE, pE, ghb2);
    k_mlp           <<<(MM + 255) / 256, 256>>>(mW1, mb1, mW2, mb2, mW3, mb3, out);
}